// round 8
// baseline (speedup 1.0000x reference)
#include <cuda_runtime.h>
#include <cfloat>
#include <math.h>

// Problem constants
#define NN 16384
#define MM 32768
#define KK 8
#define CC 256
#define GG 16                 // M-splits for KNN parallelism
#define MSEG (MM / GG)        // 2048
#define TILE 1024             // cond candidates per shared tile

// Scratch (device globals; no allocations allowed)
__device__ float g_pd[GG * NN * KK];   // partial top-8 squared dists
__device__ int   g_pi[GG * NN * KK];   // partial top-8 indices
__device__ float g_favg[NN * CC];      // weighted-average features
__device__ float g_h1[NN * CC];        // MLP intermediate 1
__device__ float g_h2[NN * CC];        // MLP intermediate 2
__device__ float g_tf[CC];             // timestep feature vector

// ---------------------------------------------------------------------------
// Kernel 1: timestep embedding -> 2-layer MLP -> g_tf[256]
// ---------------------------------------------------------------------------
__global__ void k_tfeats(const float* __restrict__ t,
                         const float* __restrict__ Wt1, const float* __restrict__ bt1,
                         const float* __restrict__ Wt2, const float* __restrict__ bt2) {
    __shared__ float emb[96];
    __shared__ float h1[96];
    int tid = threadIdx.x;
    float tv = t[0];
    if (tid < 48) {
        const double c64 = -9.210340371976184 / 47.0;
        float cf = (float)c64;
        float arg = __fmul_rn((float)tid, cf);
        float f = (float)exp((double)arg);
        float e = __fmul_rn(tv, f);
        emb[tid]      = (float)sin((double)e);
        emb[tid + 48] = (float)cos((double)e);
    }
    __syncthreads();
    if (tid < 96) {
        float acc = 0.0f;
        #pragma unroll 8
        for (int j = 0; j < 96; ++j) acc += emb[j] * Wt1[tid * 96 + j];
        acc += bt1[tid];
        h1[tid] = (acc >= 0.0f) ? acc : 0.1f * acc;
    }
    __syncthreads();
    if (tid < 256) {
        float acc = 0.0f;
        #pragma unroll 8
        for (int j = 0; j < 96; ++j) acc += h1[j] * Wt2[tid * 96 + j];
        acc += bt2[tid];
        g_tf[tid] = acc;
    }
}

// ---------------------------------------------------------------------------
// Packed f32x2 helpers (two independent IEEE-RN fp32 lanes -> bit-exact)
// ---------------------------------------------------------------------------
__device__ __forceinline__ unsigned long long pack2(float x) {
    unsigned long long r;
    asm("mov.b64 %0, {%1, %1};" : "=l"(r) : "f"(x));
    return r;
}

// d_lane = fma(dz,dz, fma(dy,dy, dx*dx)) with dx = nx + (-cx)  (XLA scheme)
__device__ __forceinline__ void dist2x2(unsigned long long nx, unsigned long long ny,
                                        unsigned long long nz,
                                        unsigned long long cx, unsigned long long cy,
                                        unsigned long long cz,
                                        float& d0, float& d1) {
    asm("{\n\t"
        ".reg .b64 dx, dy, dz, t;\n\t"
        "add.rn.f32x2 dx, %2, %5;\n\t"
        "add.rn.f32x2 dy, %3, %6;\n\t"
        "add.rn.f32x2 dz, %4, %7;\n\t"
        "mul.rn.f32x2 t, dx, dx;\n\t"
        "fma.rn.f32x2 t, dy, dy, t;\n\t"
        "fma.rn.f32x2 t, dz, dz, t;\n\t"
        "mov.b64 {%0, %1}, t;\n\t"
        "}"
        : "=f"(d0), "=f"(d1)
        : "l"(nx), "l"(ny), "l"(nz), "l"(cx), "l"(cy), "l"(cz));
}

__device__ __forceinline__ void insert8(float d, int idx, float* bd, int* bi) {
    if (d < bd[KK - 1]) {
        bd[KK - 1] = d;
        bi[KK - 1] = idx;
        #pragma unroll
        for (int q = KK - 1; q > 0; --q) {
            if (bd[q] < bd[q - 1]) {
                float td = bd[q]; bd[q] = bd[q - 1]; bd[q - 1] = td;
                int   ti = bi[q]; bi[q] = bi[q - 1]; bi[q - 1] = ti;
            }
        }
    }
}

union F4U {
    float4 v;
    unsigned long long u[2];
};

// ---------------------------------------------------------------------------
// Kernel 2: brute-force KNN, exact XLA fmla scheme, packed f32x2.
// 2 nodes/thread, 8 candidates/iteration. Guard granularity = 8 candidates:
// FMNMX tree over the 8 exact distances, ONE branch per node per 8.
// No false negatives (min8 < bd[7] iff some d < bd[7]); ties (==) correctly
// excluded in both guard and insert; body scans ascending index -> identical
// selection + tie semantics.
// ---------------------------------------------------------------------------
__global__ void __launch_bounds__(128) k_knn(const int* __restrict__ node_c,
                                             const int* __restrict__ cond_c) {
    __shared__ __align__(16) float s_nx[TILE];
    __shared__ __align__(16) float s_ny[TILE];
    __shared__ __align__(16) float s_nz[TILE];

    const int tid = threadIdx.x;
    const int n0 = blockIdx.x * 256 + tid;
    const int n1 = n0 + 128;

    const int4 ncA = ((const int4*)node_c)[n0];
    const int4 ncB = ((const int4*)node_c)[n1];
    unsigned long long nxA = pack2(__fmul_rn(__fadd_rn((float)ncA.y, 8.0f), 0.05f));
    unsigned long long nyA = pack2(__fmul_rn(__fadd_rn((float)ncA.z, 8.0f), 0.05f));
    unsigned long long nzA = pack2(__fmul_rn(__fadd_rn((float)ncA.w, 8.0f), 0.05f));
    unsigned long long nxB = pack2(__fmul_rn(__fadd_rn((float)ncB.y, 8.0f), 0.05f));
    unsigned long long nyB = pack2(__fmul_rn(__fadd_rn((float)ncB.z, 8.0f), 0.05f));
    unsigned long long nzB = pack2(__fmul_rn(__fadd_rn((float)ncB.w, 8.0f), 0.05f));

    float bdA[KK], bdB[KK];
    int   biA[KK], biB[KK];
    #pragma unroll
    for (int s = 0; s < KK; ++s) {
        bdA[s] = FLT_MAX; biA[s] = 0x7fffffff;
        bdB[s] = FLT_MAX; biB[s] = 0x7fffffff;
    }

    const int m0 = blockIdx.y * MSEG;

    for (int t0 = 0; t0 < MSEG; t0 += TILE) {
        // negated transformed candidate coords, SoA
        for (int j = tid; j < TILE; j += 128) {
            int4 cc = ((const int4*)cond_c)[m0 + t0 + j];
            s_nx[j] = -__fmul_rn(__fadd_rn((float)cc.y, 0.5f), 0.01f);
            s_ny[j] = -__fmul_rn(__fadd_rn((float)cc.z, 0.5f), 0.01f);
            s_nz[j] = -__fmul_rn(__fadd_rn((float)cc.w, 0.5f), 0.01f);
        }
        __syncthreads();

        #pragma unroll 1
        for (int j = 0; j < TILE; j += 8) {
            F4U X0, Y0, Z0, X1, Y1, Z1;
            X0.v = *(const float4*)&s_nx[j];
            Y0.v = *(const float4*)&s_ny[j];
            Z0.v = *(const float4*)&s_nz[j];
            X1.v = *(const float4*)&s_nx[j + 4];
            Y1.v = *(const float4*)&s_ny[j + 4];
            Z1.v = *(const float4*)&s_nz[j + 4];

            float dA[8], dB[8];
            dist2x2(nxA, nyA, nzA, X0.u[0], Y0.u[0], Z0.u[0], dA[0], dA[1]);
            dist2x2(nxA, nyA, nzA, X0.u[1], Y0.u[1], Z0.u[1], dA[2], dA[3]);
            dist2x2(nxA, nyA, nzA, X1.u[0], Y1.u[0], Z1.u[0], dA[4], dA[5]);
            dist2x2(nxA, nyA, nzA, X1.u[1], Y1.u[1], Z1.u[1], dA[6], dA[7]);
            dist2x2(nxB, nyB, nzB, X0.u[0], Y0.u[0], Z0.u[0], dB[0], dB[1]);
            dist2x2(nxB, nyB, nzB, X0.u[1], Y0.u[1], Z0.u[1], dB[2], dB[3]);
            dist2x2(nxB, nyB, nzB, X1.u[0], Y1.u[0], Z1.u[0], dB[4], dB[5]);
            dist2x2(nxB, nyB, nzB, X1.u[1], Y1.u[1], Z1.u[1], dB[6], dB[7]);

            float mA = fminf(fminf(fminf(dA[0], dA[1]), fminf(dA[2], dA[3])),
                             fminf(fminf(dA[4], dA[5]), fminf(dA[6], dA[7])));
            float mB = fminf(fminf(fminf(dB[0], dB[1]), fminf(dB[2], dB[3])),
                             fminf(fminf(dB[4], dB[5]), fminf(dB[6], dB[7])));

            int g = m0 + t0 + j;
            if (mA < bdA[KK - 1]) {
                #pragma unroll
                for (int q = 0; q < 8; ++q) insert8(dA[q], g + q, bdA, biA);
            }
            if (mB < bdB[KK - 1]) {
                #pragma unroll
                for (int q = 0; q < 8; ++q) insert8(dB[q], g + q, bdB, biB);
            }
        }
        __syncthreads();
    }

    int baseA = (blockIdx.y * NN + n0) * KK;
    int baseB = (blockIdx.y * NN + n1) * KK;
    #pragma unroll
    for (int s = 0; s < KK; ++s) {
        g_pd[baseA + s] = bdA[s];  g_pi[baseA + s] = biA[s];
        g_pd[baseB + s] = bdB[s];  g_pi[baseB + s] = biB[s];
    }
}

// ---------------------------------------------------------------------------
// Kernel 3: merge GG x 8 = 128 partials -> top-8, weights, weighted gather.
// One warp per node; lane owns entries lane, lane+32, lane+64, lane+96.
// ---------------------------------------------------------------------------
__global__ void __launch_bounds__(256) k_merge(const float* __restrict__ cond_feats) {
    int warp = threadIdx.x >> 5;
    int lane = threadIdx.x & 31;
    int n = blockIdx.x * 8 + warp;

    float d[4];
    int   id[4];
    #pragma unroll
    for (int q = 0; q < 4; ++q) {
        int e = lane + q * 32;
        int src = ((e >> 3) * NN + n) * KK + (e & 7);
        d[q]  = g_pd[src];
        id[q] = g_pi[src];
    }

    float wd[KK];
    int   wi[KK];
    #pragma unroll
    for (int k = 0; k < KK; ++k) {
        float cd = d[0]; int ci = id[0];
        #pragma unroll
        for (int q = 1; q < 4; ++q) {
            if (d[q] < cd || (d[q] == cd && id[q] < ci)) { cd = d[q]; ci = id[q]; }
        }
        #pragma unroll
        for (int off = 16; off > 0; off >>= 1) {
            float od = __shfl_xor_sync(0xffffffffu, cd, off);
            int   oi = __shfl_xor_sync(0xffffffffu, ci, off);
            if (od < cd || (od == cd && oi < ci)) { cd = od; ci = oi; }
        }
        wd[k] = cd; wi[k] = ci;
        #pragma unroll
        for (int q = 0; q < 4; ++q) if (id[q] == ci) d[q] = FLT_MAX;
    }

    float w[KK];
    float wsum = 0.0f;
    #pragma unroll
    for (int k = 0; k < KK; ++k) {
        float dist = fmaxf(sqrtf(wd[k]), 1e-6f);
        w[k] = 1.0f / dist;
        wsum += w[k];
    }
    #pragma unroll
    for (int k = 0; k < KK; ++k) w[k] = w[k] / wsum;

    const float* rp[KK];
    #pragma unroll
    for (int k = 0; k < KK; ++k) rp[k] = cond_feats + (size_t)wi[k] * CC;

    float* outp = g_favg + (size_t)n * CC;
    #pragma unroll
    for (int j = 0; j < 8; ++j) {
        int c = lane + j * 32;
        float acc = 0.0f;
        #pragma unroll
        for (int k = 0; k < KK; ++k) acc = fmaf(w[k], rp[k][c], acc);
        outp[c] = acc;
    }
}

// ---------------------------------------------------------------------------
// Kernel 4: register-blocked SGEMM  Y[16384,256] = X @ W^T (+bias, act, tf)
// 128x128 tile, 256 threads, 8x8 micro-tile, double-buffered smem (proven
// fastest variant: 61us, fma 44%).
// ---------------------------------------------------------------------------
#define SP 132   // smem pitch (floats)
template<int ACT, int ADDTF>
__global__ void __launch_bounds__(256, 2) k_gemm(const float* __restrict__ X,
                                                 const float* __restrict__ W,
                                                 const float* __restrict__ bias,
                                                 float* __restrict__ Y) {
    __shared__ float As[2][8][SP];
    __shared__ float Bs[2][8][SP];

    const int t   = threadIdx.x;
    const int tx  = t & 15;
    const int ty  = t >> 4;
    const int row0 = blockIdx.x * 128;
    const int col0 = blockIdx.y * 128;

    const int lrow = t >> 1;
    const int lk4  = (t & 1) * 4;
    const float* Ag = X + (size_t)(row0 + lrow) * CC + lk4;
    const float* Bg = W + (size_t)(col0 + lrow) * CC + lk4;

    float4 afrag = *(const float4*)Ag;
    float4 bfrag = *(const float4*)Bg;

    As[0][lk4 + 0][lrow] = afrag.x;
    As[0][lk4 + 1][lrow] = afrag.y;
    As[0][lk4 + 2][lrow] = afrag.z;
    As[0][lk4 + 3][lrow] = afrag.w;
    Bs[0][lk4 + 0][lrow] = bfrag.x;
    Bs[0][lk4 + 1][lrow] = bfrag.y;
    Bs[0][lk4 + 2][lrow] = bfrag.z;
    Bs[0][lk4 + 3][lrow] = bfrag.w;
    __syncthreads();

    float acc[8][8];
    #pragma unroll
    for (int i = 0; i < 8; ++i)
        #pragma unroll
        for (int j = 0; j < 8; ++j) acc[i][j] = 0.0f;

    #pragma unroll 1
    for (int kt = 0; kt < 32; ++kt) {
        int buf = kt & 1;
        if (kt < 31) {
            afrag = *(const float4*)(Ag + (kt + 1) * 8);
            bfrag = *(const float4*)(Bg + (kt + 1) * 8);
        }

        #pragma unroll
        for (int kk = 0; kk < 8; ++kk) {
            float4 a0 = *(const float4*)&As[buf][kk][ty * 8];
            float4 a1 = *(const float4*)&As[buf][kk][ty * 8 + 4];
            float4 b0 = *(const float4*)&Bs[buf][kk][tx * 8];
            float4 b1 = *(const float4*)&Bs[buf][kk][tx * 8 + 4];
            float av[8] = {a0.x, a0.y, a0.z, a0.w, a1.x, a1.y, a1.z, a1.w};
            float bv[8] = {b0.x, b0.y, b0.z, b0.w, b1.x, b1.y, b1.z, b1.w};
            #pragma unroll
            for (int i = 0; i < 8; ++i)
                #pragma unroll
                for (int j = 0; j < 8; ++j)
                    acc[i][j] = fmaf(av[i], bv[j], acc[i][j]);
        }

        if (kt < 31) {
            int nb = buf ^ 1;
            As[nb][lk4 + 0][lrow] = afrag.x;
            As[nb][lk4 + 1][lrow] = afrag.y;
            As[nb][lk4 + 2][lrow] = afrag.z;
            As[nb][lk4 + 3][lrow] = afrag.w;
            Bs[nb][lk4 + 0][lrow] = bfrag.x;
            Bs[nb][lk4 + 1][lrow] = bfrag.y;
            Bs[nb][lk4 + 2][lrow] = bfrag.z;
            Bs[nb][lk4 + 3][lrow] = bfrag.w;
            __syncthreads();
        }
    }

    float bb[8], tf[8];
    #pragma unroll
    for (int j = 0; j < 8; ++j) {
        int c = col0 + tx * 8 + j;
        bb[j] = bias[c];
        if (ADDTF) tf[j] = g_tf[c];
    }

    #pragma unroll
    for (int i = 0; i < 8; ++i) {
        int r = row0 + ty * 8 + i;
        float o[8];
        #pragma unroll
        for (int j = 0; j < 8; ++j) {
            float v = acc[i][j] + bb[j];
            if (ACT)   v = (v >= 0.0f) ? v : 0.1f * v;
            if (ADDTF) v = v + tf[j];
            o[j] = v;
        }
        float4* yp = (float4*)(Y + (size_t)r * CC + col0 + tx * 8);
        yp[0] = make_float4(o[0], o[1], o[2], o[3]);
        yp[1] = make_float4(o[4], o[5], o[6], o[7]);
    }
}

// ---------------------------------------------------------------------------
extern "C" void kernel_launch(void* const* d_in, const int* in_sizes, int n_in,
                              void* d_out, int out_size) {
    const int*   node_c     = (const int*)d_in[0];
    const int*   cond_c     = (const int*)d_in[1];
    const float* cond_feats = (const float*)d_in[2];
    const float* t          = (const float*)d_in[3];
    const float* W_proj     = (const float*)d_in[4];
    const float* b_proj     = (const float*)d_in[5];
    const float* W_l1       = (const float*)d_in[6];
    const float* b_l1       = (const float*)d_in[7];
    const float* W_l2       = (const float*)d_in[8];
    const float* b_l2       = (const float*)d_in[9];
    const float* W_t1       = (const float*)d_in[10];
    const float* b_t1       = (const float*)d_in[11];
    const float* W_t2       = (const float*)d_in[12];
    const float* b_t2       = (const float*)d_in[13];
    float* out = (float*)d_out;

    float* h1; cudaGetSymbolAddress((void**)&h1, g_h1);
    float* h2; cudaGetSymbolAddress((void**)&h2, g_h2);
    float* fa; cudaGetSymbolAddress((void**)&fa, g_favg);

    k_tfeats<<<1, 256>>>(t, W_t1, b_t1, W_t2, b_t2);

    dim3 gknn(NN / 256, GG);       // 64 x 16 blocks, 128 threads (2 nodes/thread)
    k_knn<<<gknn, 128>>>(node_c, cond_c);

    k_merge<<<NN / 8, 256>>>(cond_feats);

    dim3 gg(NN / 128, CC / 128);   // 128 x 2 = 256 blocks
    k_gemm<0, 0><<<gg, 256>>>(fa, W_proj, b_proj, h1);
    k_gemm<1, 0><<<gg, 256>>>(h1, W_l1, b_l1, h2);
    k_gemm<0, 1><<<gg, 256>>>(h2, W_l2, b_l2, out);

    (void)in_sizes; (void)n_in; (void)out_size;
}

// round 9
// speedup vs baseline: 1.0503x; 1.0503x over previous
#include <cuda_runtime.h>
#include <cfloat>
#include <math.h>

// Problem constants
#define NN 16384
#define MM 32768
#define KK 8
#define CC 256
#define TILE 2048             // cond candidates per shared tile
#define NTILES (MM / TILE)    // 16

// Scratch (device globals; no allocations allowed)
__device__ __align__(16) float g_cx[MM];   // negated transformed cond x
__device__ __align__(16) float g_cy[MM];
__device__ __align__(16) float g_cz[MM];
__device__ float g_favg[NN * CC];      // weighted-average features
__device__ float g_h1[NN * CC];        // MLP intermediate 1
__device__ float g_h2[NN * CC];        // MLP intermediate 2
__device__ float g_tf[CC];             // timestep feature vector

// ---------------------------------------------------------------------------
// Kernel 0: pre-transform cond coords (negated, SoA)
// ---------------------------------------------------------------------------
__global__ void k_prep(const int* __restrict__ cond_c) {
    int i = blockIdx.x * 256 + threadIdx.x;
    int4 cc = ((const int4*)cond_c)[i];
    g_cx[i] = -__fmul_rn(__fadd_rn((float)cc.y, 0.5f), 0.01f);
    g_cy[i] = -__fmul_rn(__fadd_rn((float)cc.z, 0.5f), 0.01f);
    g_cz[i] = -__fmul_rn(__fadd_rn((float)cc.w, 0.5f), 0.01f);
}

// ---------------------------------------------------------------------------
// Kernel 1: timestep embedding -> 2-layer MLP -> g_tf[256]
// ---------------------------------------------------------------------------
__global__ void k_tfeats(const float* __restrict__ t,
                         const float* __restrict__ Wt1, const float* __restrict__ bt1,
                         const float* __restrict__ Wt2, const float* __restrict__ bt2) {
    __shared__ float emb[96];
    __shared__ float h1[96];
    int tid = threadIdx.x;
    float tv = t[0];
    if (tid < 48) {
        const double c64 = -9.210340371976184 / 47.0;
        float cf = (float)c64;
        float arg = __fmul_rn((float)tid, cf);
        float f = (float)exp((double)arg);
        float e = __fmul_rn(tv, f);
        emb[tid]      = (float)sin((double)e);
        emb[tid + 48] = (float)cos((double)e);
    }
    __syncthreads();
    if (tid < 96) {
        float acc = 0.0f;
        #pragma unroll 8
        for (int j = 0; j < 96; ++j) acc += emb[j] * Wt1[tid * 96 + j];
        acc += bt1[tid];
        h1[tid] = (acc >= 0.0f) ? acc : 0.1f * acc;
    }
    __syncthreads();
    if (tid < 256) {
        float acc = 0.0f;
        #pragma unroll 8
        for (int j = 0; j < 96; ++j) acc += h1[j] * Wt2[tid * 96 + j];
        acc += bt2[tid];
        g_tf[tid] = acc;
    }
}

// ---------------------------------------------------------------------------
// Packed f32x2 helpers (two independent IEEE-RN fp32 lanes -> bit-exact)
// ---------------------------------------------------------------------------
__device__ __forceinline__ unsigned long long pack2(float x) {
    unsigned long long r;
    asm("mov.b64 %0, {%1, %1};" : "=l"(r) : "f"(x));
    return r;
}

// d_lane = fma(dz,dz, fma(dy,dy, dx*dx)) with dx = nx + (-cx)  (XLA scheme)
__device__ __forceinline__ void dist2x2(unsigned long long nx, unsigned long long ny,
                                        unsigned long long nz,
                                        unsigned long long cx, unsigned long long cy,
                                        unsigned long long cz,
                                        float& d0, float& d1) {
    asm("{\n\t"
        ".reg .b64 dx, dy, dz, t;\n\t"
        "add.rn.f32x2 dx, %2, %5;\n\t"
        "add.rn.f32x2 dy, %3, %6;\n\t"
        "add.rn.f32x2 dz, %4, %7;\n\t"
        "mul.rn.f32x2 t, dx, dx;\n\t"
        "fma.rn.f32x2 t, dy, dy, t;\n\t"
        "fma.rn.f32x2 t, dz, dz, t;\n\t"
        "mov.b64 {%0, %1}, t;\n\t"
        "}"
        : "=f"(d0), "=f"(d1)
        : "l"(nx), "l"(ny), "l"(nz), "l"(cx), "l"(cy), "l"(cz));
}

// Sorted insert, strict '<' (ties keep earlier=lower-index entry) — matches
// the reference top_k semantics when candidates arrive in ascending index.
__device__ __forceinline__ void insert8(float d, int idx, float* bd, int* bi) {
    if (d < bd[KK - 1]) {
        bd[KK - 1] = d;
        bi[KK - 1] = idx;
        #pragma unroll
        for (int q = KK - 1; q > 0; --q) {
            if (bd[q] < bd[q - 1]) {
                float td = bd[q]; bd[q] = bd[q - 1]; bd[q - 1] = td;
                int   ti = bi[q]; bi[q] = bi[q - 1]; bi[q - 1] = ti;
            }
        }
    }
}

union F4U {
    float4 v;
    unsigned long long u[2];
};

// ---------------------------------------------------------------------------
// Kernel 2: warp-cooperative KNN + weights + feature gather, fused.
// One warp processes 2 nodes over ALL 32768 candidates (no partials/merge).
// All 32 lanes share one node's selection state (replicated registers), so
// insert events are warp-correlated: __ballot guard skips ~85% of windows
// uniformly. Candidates processed in ascending index (ffs from LSB), exact
// XLA fmla distances -> selection + ties bit-identical to reference.
// ---------------------------------------------------------------------------
__global__ void __launch_bounds__(256) k_knn(const int* __restrict__ node_c,
                                             const float* __restrict__ cond_feats) {
    __shared__ __align__(16) float sx[TILE];
    __shared__ __align__(16) float sy[TILE];
    __shared__ __align__(16) float sz[TILE];

    const int tid  = threadIdx.x;
    const int warp = tid >> 5;
    const int lane = tid & 31;
    const int nbase = blockIdx.x * 16 + warp * 2;   // 8 warps x 2 nodes
    const unsigned FULL = 0xffffffffu;

    // node coords (uniform broadcast loads), packed into both f32x2 lanes
    unsigned long long nx[2], ny[2], nz[2];
    #pragma unroll
    for (int u = 0; u < 2; ++u) {
        int4 nc = ((const int4*)node_c)[nbase + u];
        nx[u] = pack2(__fmul_rn(__fadd_rn((float)nc.y, 8.0f), 0.05f));
        ny[u] = pack2(__fmul_rn(__fadd_rn((float)nc.z, 8.0f), 0.05f));
        nz[u] = pack2(__fmul_rn(__fadd_rn((float)nc.w, 8.0f), 0.05f));
    }

    float bd0[KK], bd1[KK];
    int   bi0[KK], bi1[KK];
    #pragma unroll
    for (int s = 0; s < KK; ++s) {
        bd0[s] = FLT_MAX; bi0[s] = 0x7fffffff;
        bd1[s] = FLT_MAX; bi1[s] = 0x7fffffff;
    }
    float thr0 = FLT_MAX, thr1 = FLT_MAX;

    for (int tile = 0; tile < NTILES; ++tile) {
        __syncthreads();
        // cooperative tile load: 2048 floats per array, 2 float4 per thread
        {
            const float4* gx = (const float4*)g_cx + tile * (TILE / 4);
            const float4* gy = (const float4*)g_cy + tile * (TILE / 4);
            const float4* gz = (const float4*)g_cz + tile * (TILE / 4);
            #pragma unroll
            for (int i = 0; i < TILE / 4 / 256 * 256; i += 256) {
                ((float4*)sx)[i + tid] = gx[i + tid];
                ((float4*)sy)[i + tid] = gy[i + tid];
                ((float4*)sz)[i + tid] = gz[i + tid];
            }
        }
        __syncthreads();

        #pragma unroll 1
        for (int step = 0; step < TILE / 128; ++step) {
            const int jb = step * 128 + lane * 4;
            F4U X, Y, Z;
            X.v = *(const float4*)&sx[jb];
            Y.v = *(const float4*)&sy[jb];
            Z.v = *(const float4*)&sz[jb];
            const int gbase = tile * TILE + step * 128;

            // ---- node 0 ----
            {
                float d0, d1, d2, d3;
                dist2x2(nx[0], ny[0], nz[0], X.u[0], Y.u[0], Z.u[0], d0, d1);
                dist2x2(nx[0], ny[0], nz[0], X.u[1], Y.u[1], Z.u[1], d2, d3);
                float mn = fminf(fminf(d0, d1), fminf(d2, d3));
                unsigned mask = __ballot_sync(FULL, mn < thr0);
                while (mask) {
                    int b = __ffs(mask) - 1; mask &= mask - 1;
                    float e0 = __shfl_sync(FULL, d0, b);
                    float e1 = __shfl_sync(FULL, d1, b);
                    float e2 = __shfl_sync(FULL, d2, b);
                    float e3 = __shfl_sync(FULL, d3, b);
                    int gi = gbase + b * 4;
                    insert8(e0, gi,     bd0, bi0);
                    insert8(e1, gi + 1, bd0, bi0);
                    insert8(e2, gi + 2, bd0, bi0);
                    insert8(e3, gi + 3, bd0, bi0);
                    thr0 = bd0[KK - 1];
                }
            }
            // ---- node 1 ----
            {
                float d0, d1, d2, d3;
                dist2x2(nx[1], ny[1], nz[1], X.u[0], Y.u[0], Z.u[0], d0, d1);
                dist2x2(nx[1], ny[1], nz[1], X.u[1], Y.u[1], Z.u[1], d2, d3);
                float mn = fminf(fminf(d0, d1), fminf(d2, d3));
                unsigned mask = __ballot_sync(FULL, mn < thr1);
                while (mask) {
                    int b = __ffs(mask) - 1; mask &= mask - 1;
                    float e0 = __shfl_sync(FULL, d0, b);
                    float e1 = __shfl_sync(FULL, d1, b);
                    float e2 = __shfl_sync(FULL, d2, b);
                    float e3 = __shfl_sync(FULL, d3, b);
                    int gi = gbase + b * 4;
                    insert8(e0, gi,     bd1, bi1);
                    insert8(e1, gi + 1, bd1, bi1);
                    insert8(e2, gi + 2, bd1, bi1);
                    insert8(e3, gi + 3, bd1, bi1);
                    thr1 = bd1[KK - 1];
                }
            }
        }
    }

    // Fused epilogue: weights + weighted feature gather (state replicated in
    // all lanes; bd ascending = reference order for the fp weight sums).
    #pragma unroll
    for (int u = 0; u < 2; ++u) {
        const float* bd = (u == 0) ? bd0 : bd1;
        const int*   bi = (u == 0) ? bi0 : bi1;

        float w[KK];
        float wsum = 0.0f;
        #pragma unroll
        for (int k = 0; k < KK; ++k) {
            float dist = fmaxf(sqrtf(bd[k]), 1e-6f);
            w[k] = 1.0f / dist;
            wsum += w[k];
        }
        #pragma unroll
        for (int k = 0; k < KK; ++k) w[k] = w[k] / wsum;

        const float* rp[KK];
        #pragma unroll
        for (int k = 0; k < KK; ++k) rp[k] = cond_feats + (size_t)bi[k] * CC;

        float* outp = g_favg + (size_t)(nbase + u) * CC;
        #pragma unroll
        for (int j = 0; j < 8; ++j) {
            int c = lane + j * 32;
            float acc = 0.0f;
            #pragma unroll
            for (int k = 0; k < KK; ++k) acc = fmaf(w[k], rp[k][c], acc);
            outp[c] = acc;
        }
    }
}

// ---------------------------------------------------------------------------
// Kernel 4: register-blocked SGEMM  Y[16384,256] = X @ W^T (+bias, act, tf)
// 128x128 tile, 256 threads, 8x8 micro-tile, double-buffered smem (proven
// fastest variant: 61us, fma 44%).
// ---------------------------------------------------------------------------
#define SP 132   // smem pitch (floats)
template<int ACT, int ADDTF>
__global__ void __launch_bounds__(256, 2) k_gemm(const float* __restrict__ X,
                                                 const float* __restrict__ W,
                                                 const float* __restrict__ bias,
                                                 float* __restrict__ Y) {
    __shared__ float As[2][8][SP];
    __shared__ float Bs[2][8][SP];

    const int t   = threadIdx.x;
    const int tx  = t & 15;
    const int ty  = t >> 4;
    const int row0 = blockIdx.x * 128;
    const int col0 = blockIdx.y * 128;

    const int lrow = t >> 1;
    const int lk4  = (t & 1) * 4;
    const float* Ag = X + (size_t)(row0 + lrow) * CC + lk4;
    const float* Bg = W + (size_t)(col0 + lrow) * CC + lk4;

    float4 afrag = *(const float4*)Ag;
    float4 bfrag = *(const float4*)Bg;

    As[0][lk4 + 0][lrow] = afrag.x;
    As[0][lk4 + 1][lrow] = afrag.y;
    As[0][lk4 + 2][lrow] = afrag.z;
    As[0][lk4 + 3][lrow] = afrag.w;
    Bs[0][lk4 + 0][lrow] = bfrag.x;
    Bs[0][lk4 + 1][lrow] = bfrag.y;
    Bs[0][lk4 + 2][lrow] = bfrag.z;
    Bs[0][lk4 + 3][lrow] = bfrag.w;
    __syncthreads();

    float acc[8][8];
    #pragma unroll
    for (int i = 0; i < 8; ++i)
        #pragma unroll
        for (int j = 0; j < 8; ++j) acc[i][j] = 0.0f;

    #pragma unroll 1
    for (int kt = 0; kt < 32; ++kt) {
        int buf = kt & 1;
        if (kt < 31) {
            afrag = *(const float4*)(Ag + (kt + 1) * 8);
            bfrag = *(const float4*)(Bg + (kt + 1) * 8);
        }

        #pragma unroll
        for (int kk = 0; kk < 8; ++kk) {
            float4 a0 = *(const float4*)&As[buf][kk][ty * 8];
            float4 a1 = *(const float4*)&As[buf][kk][ty * 8 + 4];
            float4 b0 = *(const float4*)&Bs[buf][kk][tx * 8];
            float4 b1 = *(const float4*)&Bs[buf][kk][tx * 8 + 4];
            float av[8] = {a0.x, a0.y, a0.z, a0.w, a1.x, a1.y, a1.z, a1.w};
            float bv[8] = {b0.x, b0.y, b0.z, b0.w, b1.x, b1.y, b1.z, b1.w};
            #pragma unroll
            for (int i = 0; i < 8; ++i)
                #pragma unroll
                for (int j = 0; j < 8; ++j)
                    acc[i][j] = fmaf(av[i], bv[j], acc[i][j]);
        }

        if (kt < 31) {
            int nb = buf ^ 1;
            As[nb][lk4 + 0][lrow] = afrag.x;
            As[nb][lk4 + 1][lrow] = afrag.y;
            As[nb][lk4 + 2][lrow] = afrag.z;
            As[nb][lk4 + 3][lrow] = afrag.w;
            Bs[nb][lk4 + 0][lrow] = bfrag.x;
            Bs[nb][lk4 + 1][lrow] = bfrag.y;
            Bs[nb][lk4 + 2][lrow] = bfrag.z;
            Bs[nb][lk4 + 3][lrow] = bfrag.w;
            __syncthreads();
        }
    }

    float bb[8], tf[8];
    #pragma unroll
    for (int j = 0; j < 8; ++j) {
        int c = col0 + tx * 8 + j;
        bb[j] = bias[c];
        if (ADDTF) tf[j] = g_tf[c];
    }

    #pragma unroll
    for (int i = 0; i < 8; ++i) {
        int r = row0 + ty * 8 + i;
        float o[8];
        #pragma unroll
        for (int j = 0; j < 8; ++j) {
            float v = acc[i][j] + bb[j];
            if (ACT)   v = (v >= 0.0f) ? v : 0.1f * v;
            if (ADDTF) v = v + tf[j];
            o[j] = v;
        }
        float4* yp = (float4*)(Y + (size_t)r * CC + col0 + tx * 8);
        yp[0] = make_float4(o[0], o[1], o[2], o[3]);
        yp[1] = make_float4(o[4], o[5], o[6], o[7]);
    }
}

// ---------------------------------------------------------------------------
extern "C" void kernel_launch(void* const* d_in, const int* in_sizes, int n_in,
                              void* d_out, int out_size) {
    const int*   node_c     = (const int*)d_in[0];
    const int*   cond_c     = (const int*)d_in[1];
    const float* cond_feats = (const float*)d_in[2];
    const float* t          = (const float*)d_in[3];
    const float* W_proj     = (const float*)d_in[4];
    const float* b_proj     = (const float*)d_in[5];
    const float* W_l1       = (const float*)d_in[6];
    const float* b_l1       = (const float*)d_in[7];
    const float* W_l2       = (const float*)d_in[8];
    const float* b_l2       = (const float*)d_in[9];
    const float* W_t1       = (const float*)d_in[10];
    const float* b_t1       = (const float*)d_in[11];
    const float* W_t2       = (const float*)d_in[12];
    const float* b_t2       = (const float*)d_in[13];
    float* out = (float*)d_out;

    float* h1; cudaGetSymbolAddress((void**)&h1, g_h1);
    float* h2; cudaGetSymbolAddress((void**)&h2, g_h2);
    float* fa; cudaGetSymbolAddress((void**)&fa, g_favg);

    k_prep<<<MM / 256, 256>>>(cond_c);
    k_tfeats<<<1, 256>>>(t, W_t1, b_t1, W_t2, b_t2);

    k_knn<<<NN / 16, 256>>>(node_c, cond_feats);   // 1024 blocks, 8 warps x 2 nodes

    dim3 gg(NN / 128, CC / 128);   // 128 x 2 = 256 blocks
    k_gemm<0, 0><<<gg, 256>>>(fa, W_proj, b_proj, h1);
    k_gemm<1, 0><<<gg, 256>>>(h1, W_l1, b_l1, h2);
    k_gemm<0, 1><<<gg, 256>>>(h2, W_l2, b_l2, out);

    (void)in_sizes; (void)n_in; (void)out_size;
}

// round 10
// speedup vs baseline: 1.0575x; 1.0069x over previous
#include <cuda_runtime.h>
#include <cfloat>
#include <math.h>

// Problem constants
#define NN 16384
#define MM 32768
#define KK 8
#define CC 256
#define TILE 2048             // cond candidates per shared tile
#define NTILES (MM / TILE)    // 16

// Scratch (device globals; no allocations allowed)
__device__ __align__(16) float g_cx[MM];   // negated transformed cond x
__device__ __align__(16) float g_cy[MM];
__device__ __align__(16) float g_cz[MM];
__device__ float g_favg[NN * CC];      // weighted-average features
__device__ float g_h1[NN * CC];        // MLP intermediate 1
__device__ float g_h2[NN * CC];        // MLP intermediate 2
__device__ float g_tf[CC];             // timestep feature vector

// ---------------------------------------------------------------------------
// Kernel 0: pre-transform cond coords (negated, SoA)
// ---------------------------------------------------------------------------
__global__ void k_prep(const int* __restrict__ cond_c) {
    int i = blockIdx.x * 256 + threadIdx.x;
    int4 cc = ((const int4*)cond_c)[i];
    g_cx[i] = -__fmul_rn(__fadd_rn((float)cc.y, 0.5f), 0.01f);
    g_cy[i] = -__fmul_rn(__fadd_rn((float)cc.z, 0.5f), 0.01f);
    g_cz[i] = -__fmul_rn(__fadd_rn((float)cc.w, 0.5f), 0.01f);
}

// ---------------------------------------------------------------------------
// Kernel 1: timestep embedding -> 2-layer MLP -> g_tf[256]
// ---------------------------------------------------------------------------
__global__ void k_tfeats(const float* __restrict__ t,
                         const float* __restrict__ Wt1, const float* __restrict__ bt1,
                         const float* __restrict__ Wt2, const float* __restrict__ bt2) {
    __shared__ float emb[96];
    __shared__ float h1[96];
    int tid = threadIdx.x;
    float tv = t[0];
    if (tid < 48) {
        const double c64 = -9.210340371976184 / 47.0;
        float cf = (float)c64;
        float arg = __fmul_rn((float)tid, cf);
        float f = (float)exp((double)arg);
        float e = __fmul_rn(tv, f);
        emb[tid]      = (float)sin((double)e);
        emb[tid + 48] = (float)cos((double)e);
    }
    __syncthreads();
    if (tid < 96) {
        float acc = 0.0f;
        #pragma unroll 8
        for (int j = 0; j < 96; ++j) acc += emb[j] * Wt1[tid * 96 + j];
        acc += bt1[tid];
        h1[tid] = (acc >= 0.0f) ? acc : 0.1f * acc;
    }
    __syncthreads();
    if (tid < 256) {
        float acc = 0.0f;
        #pragma unroll 8
        for (int j = 0; j < 96; ++j) acc += h1[j] * Wt2[tid * 96 + j];
        acc += bt2[tid];
        g_tf[tid] = acc;
    }
}

// ---------------------------------------------------------------------------
// Packed f32x2 helpers (two independent IEEE-RN fp32 lanes -> bit-exact)
// ---------------------------------------------------------------------------
__device__ __forceinline__ unsigned long long pack2(float x) {
    unsigned long long r;
    asm("mov.b64 %0, {%1, %1};" : "=l"(r) : "f"(x));
    return r;
}

__device__ __forceinline__ void ffma2(unsigned long long& acc,
                                      unsigned long long a, unsigned long long b) {
    asm("fma.rn.f32x2 %0, %1, %2, %0;" : "+l"(acc) : "l"(a), "l"(b));
}

__device__ __forceinline__ void unpack2(unsigned long long v, float& lo, float& hi) {
    asm("mov.b64 {%0, %1}, %2;" : "=f"(lo), "=f"(hi) : "l"(v));
}

// d_lane = fma(dz,dz, fma(dy,dy, dx*dx)) with dx = nx + (-cx)  (XLA scheme)
__device__ __forceinline__ void dist2x2(unsigned long long nx, unsigned long long ny,
                                        unsigned long long nz,
                                        unsigned long long cx, unsigned long long cy,
                                        unsigned long long cz,
                                        float& d0, float& d1) {
    asm("{\n\t"
        ".reg .b64 dx, dy, dz, t;\n\t"
        "add.rn.f32x2 dx, %2, %5;\n\t"
        "add.rn.f32x2 dy, %3, %6;\n\t"
        "add.rn.f32x2 dz, %4, %7;\n\t"
        "mul.rn.f32x2 t, dx, dx;\n\t"
        "fma.rn.f32x2 t, dy, dy, t;\n\t"
        "fma.rn.f32x2 t, dz, dz, t;\n\t"
        "mov.b64 {%0, %1}, t;\n\t"
        "}"
        : "=f"(d0), "=f"(d1)
        : "l"(nx), "l"(ny), "l"(nz), "l"(cx), "l"(cy), "l"(cz));
}

// Sorted insert, strict '<' (ties keep earlier=lower-index entry) — matches
// the reference top_k semantics when candidates arrive in ascending index.
__device__ __forceinline__ void insert8(float d, int idx, float* bd, int* bi) {
    if (d < bd[KK - 1]) {
        bd[KK - 1] = d;
        bi[KK - 1] = idx;
        #pragma unroll
        for (int q = KK - 1; q > 0; --q) {
            if (bd[q] < bd[q - 1]) {
                float td = bd[q]; bd[q] = bd[q - 1]; bd[q - 1] = td;
                int   ti = bi[q]; bi[q] = bi[q - 1]; bi[q - 1] = ti;
            }
        }
    }
}

union F4U {
    float4 v;
    unsigned long long u[2];
};

// ---------------------------------------------------------------------------
// Kernel 2: warp-cooperative KNN + weights + feature gather, fused.
// (unchanged from round 9 — proven 497.7us configuration)
// ---------------------------------------------------------------------------
__global__ void __launch_bounds__(256) k_knn(const int* __restrict__ node_c,
                                             const float* __restrict__ cond_feats) {
    __shared__ __align__(16) float sx[TILE];
    __shared__ __align__(16) float sy[TILE];
    __shared__ __align__(16) float sz[TILE];

    const int tid  = threadIdx.x;
    const int warp = tid >> 5;
    const int lane = tid & 31;
    const int nbase = blockIdx.x * 16 + warp * 2;   // 8 warps x 2 nodes
    const unsigned FULL = 0xffffffffu;

    unsigned long long nx[2], ny[2], nz[2];
    #pragma unroll
    for (int u = 0; u < 2; ++u) {
        int4 nc = ((const int4*)node_c)[nbase + u];
        nx[u] = pack2(__fmul_rn(__fadd_rn((float)nc.y, 8.0f), 0.05f));
        ny[u] = pack2(__fmul_rn(__fadd_rn((float)nc.z, 8.0f), 0.05f));
        nz[u] = pack2(__fmul_rn(__fadd_rn((float)nc.w, 8.0f), 0.05f));
    }

    float bd0[KK], bd1[KK];
    int   bi0[KK], bi1[KK];
    #pragma unroll
    for (int s = 0; s < KK; ++s) {
        bd0[s] = FLT_MAX; bi0[s] = 0x7fffffff;
        bd1[s] = FLT_MAX; bi1[s] = 0x7fffffff;
    }
    float thr0 = FLT_MAX, thr1 = FLT_MAX;

    for (int tile = 0; tile < NTILES; ++tile) {
        __syncthreads();
        {
            const float4* gx = (const float4*)g_cx + tile * (TILE / 4);
            const float4* gy = (const float4*)g_cy + tile * (TILE / 4);
            const float4* gz = (const float4*)g_cz + tile * (TILE / 4);
            #pragma unroll
            for (int i = 0; i < TILE / 4 / 256 * 256; i += 256) {
                ((float4*)sx)[i + tid] = gx[i + tid];
                ((float4*)sy)[i + tid] = gy[i + tid];
                ((float4*)sz)[i + tid] = gz[i + tid];
            }
        }
        __syncthreads();

        #pragma unroll 1
        for (int step = 0; step < TILE / 128; ++step) {
            const int jb = step * 128 + lane * 4;
            F4U X, Y, Z;
            X.v = *(const float4*)&sx[jb];
            Y.v = *(const float4*)&sy[jb];
            Z.v = *(const float4*)&sz[jb];
            const int gbase = tile * TILE + step * 128;

            // ---- node 0 ----
            {
                float d0, d1, d2, d3;
                dist2x2(nx[0], ny[0], nz[0], X.u[0], Y.u[0], Z.u[0], d0, d1);
                dist2x2(nx[0], ny[0], nz[0], X.u[1], Y.u[1], Z.u[1], d2, d3);
                float mn = fminf(fminf(d0, d1), fminf(d2, d3));
                unsigned mask = __ballot_sync(FULL, mn < thr0);
                while (mask) {
                    int b = __ffs(mask) - 1; mask &= mask - 1;
                    float e0 = __shfl_sync(FULL, d0, b);
                    float e1 = __shfl_sync(FULL, d1, b);
                    float e2 = __shfl_sync(FULL, d2, b);
                    float e3 = __shfl_sync(FULL, d3, b);
                    int gi = gbase + b * 4;
                    insert8(e0, gi,     bd0, bi0);
                    insert8(e1, gi + 1, bd0, bi0);
                    insert8(e2, gi + 2, bd0, bi0);
                    insert8(e3, gi + 3, bd0, bi0);
                    thr0 = bd0[KK - 1];
                }
            }
            // ---- node 1 ----
            {
                float d0, d1, d2, d3;
                dist2x2(nx[1], ny[1], nz[1], X.u[0], Y.u[0], Z.u[0], d0, d1);
                dist2x2(nx[1], ny[1], nz[1], X.u[1], Y.u[1], Z.u[1], d2, d3);
                float mn = fminf(fminf(d0, d1), fminf(d2, d3));
                unsigned mask = __ballot_sync(FULL, mn < thr1);
                while (mask) {
                    int b = __ffs(mask) - 1; mask &= mask - 1;
                    float e0 = __shfl_sync(FULL, d0, b);
                    float e1 = __shfl_sync(FULL, d1, b);
                    float e2 = __shfl_sync(FULL, d2, b);
                    float e3 = __shfl_sync(FULL, d3, b);
                    int gi = gbase + b * 4;
                    insert8(e0, gi,     bd1, bi1);
                    insert8(e1, gi + 1, bd1, bi1);
                    insert8(e2, gi + 2, bd1, bi1);
                    insert8(e3, gi + 3, bd1, bi1);
                    thr1 = bd1[KK - 1];
                }
            }
        }
    }

    #pragma unroll
    for (int u = 0; u < 2; ++u) {
        const float* bd = (u == 0) ? bd0 : bd1;
        const int*   bi = (u == 0) ? bi0 : bi1;

        float w[KK];
        float wsum = 0.0f;
        #pragma unroll
        for (int k = 0; k < KK; ++k) {
            float dist = fmaxf(sqrtf(bd[k]), 1e-6f);
            w[k] = 1.0f / dist;
            wsum += w[k];
        }
        #pragma unroll
        for (int k = 0; k < KK; ++k) w[k] = w[k] / wsum;

        const float* rp[KK];
        #pragma unroll
        for (int k = 0; k < KK; ++k) rp[k] = cond_feats + (size_t)bi[k] * CC;

        float* outp = g_favg + (size_t)(nbase + u) * CC;
        #pragma unroll
        for (int j = 0; j < 8; ++j) {
            int c = lane + j * 32;
            float acc = 0.0f;
            #pragma unroll
            for (int k = 0; k < KK; ++k) acc = fmaf(w[k], rp[k][c], acc);
            outp[c] = acc;
        }
    }
}

// ---------------------------------------------------------------------------
// Kernel 4: packed-f32x2 SGEMM  Y[16384,256] = X @ W^T (+bias, act, tf)
// 128x128 tile, 256 threads, 8x8 micro-tile accumulated as 4 row-pairs x 8
// cols in b64 (FFMA2: 2 MACs per fma-pipe issue). A row-pairs come packed
// for free from the transposed smem layout; B cols duplicated via 1 mov each.
// Each packed lane executes the identical scalar fmaf sequence in identical
// k-order -> bit-identical to the scalar version.
// ---------------------------------------------------------------------------
#define SP 132   // smem pitch (floats)
template<int ACT, int ADDTF>
__global__ void __launch_bounds__(256, 2) k_gemm(const float* __restrict__ X,
                                                 const float* __restrict__ W,
                                                 const float* __restrict__ bias,
                                                 float* __restrict__ Y) {
    __shared__ float As[2][8][SP];
    __shared__ float Bs[2][8][SP];

    const int t   = threadIdx.x;
    const int tx  = t & 15;
    const int ty  = t >> 4;
    const int row0 = blockIdx.x * 128;
    const int col0 = blockIdx.y * 128;

    const int lrow = t >> 1;
    const int lk4  = (t & 1) * 4;
    const float* Ag = X + (size_t)(row0 + lrow) * CC + lk4;
    const float* Bg = W + (size_t)(col0 + lrow) * CC + lk4;

    float4 afrag = *(const float4*)Ag;
    float4 bfrag = *(const float4*)Bg;

    As[0][lk4 + 0][lrow] = afrag.x;
    As[0][lk4 + 1][lrow] = afrag.y;
    As[0][lk4 + 2][lrow] = afrag.z;
    As[0][lk4 + 3][lrow] = afrag.w;
    Bs[0][lk4 + 0][lrow] = bfrag.x;
    Bs[0][lk4 + 1][lrow] = bfrag.y;
    Bs[0][lk4 + 2][lrow] = bfrag.z;
    Bs[0][lk4 + 3][lrow] = bfrag.w;
    __syncthreads();

    // acc2[i2][j]: lanes = rows (ty*8 + 2*i2, ty*8 + 2*i2 + 1), column j
    unsigned long long acc2[4][8];
    #pragma unroll
    for (int i = 0; i < 4; ++i)
        #pragma unroll
        for (int j = 0; j < 8; ++j) acc2[i][j] = 0ull;

    #pragma unroll 1
    for (int kt = 0; kt < 32; ++kt) {
        int buf = kt & 1;
        if (kt < 31) {
            afrag = *(const float4*)(Ag + (kt + 1) * 8);
            bfrag = *(const float4*)(Bg + (kt + 1) * 8);
        }

        #pragma unroll
        for (int kk = 0; kk < 8; ++kk) {
            F4U a0, a1, b0, b1;
            a0.v = *(const float4*)&As[buf][kk][ty * 8];
            a1.v = *(const float4*)&As[buf][kk][ty * 8 + 4];
            b0.v = *(const float4*)&Bs[buf][kk][tx * 8];
            b1.v = *(const float4*)&Bs[buf][kk][tx * 8 + 4];

            unsigned long long ap[4] = {a0.u[0], a0.u[1], a1.u[0], a1.u[1]};
            unsigned long long bp[8];
            bp[0] = pack2(b0.v.x); bp[1] = pack2(b0.v.y);
            bp[2] = pack2(b0.v.z); bp[3] = pack2(b0.v.w);
            bp[4] = pack2(b1.v.x); bp[5] = pack2(b1.v.y);
            bp[6] = pack2(b1.v.z); bp[7] = pack2(b1.v.w);

            #pragma unroll
            for (int i = 0; i < 4; ++i)
                #pragma unroll
                for (int j = 0; j < 8; ++j)
                    ffma2(acc2[i][j], ap[i], bp[j]);
        }

        if (kt < 31) {
            int nb = buf ^ 1;
            As[nb][lk4 + 0][lrow] = afrag.x;
            As[nb][lk4 + 1][lrow] = afrag.y;
            As[nb][lk4 + 2][lrow] = afrag.z;
            As[nb][lk4 + 3][lrow] = afrag.w;
            Bs[nb][lk4 + 0][lrow] = bfrag.x;
            Bs[nb][lk4 + 1][lrow] = bfrag.y;
            Bs[nb][lk4 + 2][lrow] = bfrag.z;
            Bs[nb][lk4 + 3][lrow] = bfrag.w;
            __syncthreads();
        }
    }

    float bb[8], tf[8];
    #pragma unroll
    for (int j = 0; j < 8; ++j) {
        int c = col0 + tx * 8 + j;
        bb[j] = bias[c];
        if (ADDTF) tf[j] = g_tf[c];
    }

    #pragma unroll
    for (int i2 = 0; i2 < 4; ++i2) {
        float oL[8], oH[8];
        #pragma unroll
        for (int j = 0; j < 8; ++j) {
            float lo, hi;
            unpack2(acc2[i2][j], lo, hi);
            float vL = lo + bb[j];
            float vH = hi + bb[j];
            if (ACT) {
                vL = (vL >= 0.0f) ? vL : 0.1f * vL;
                vH = (vH >= 0.0f) ? vH : 0.1f * vH;
            }
            if (ADDTF) { vL += tf[j]; vH += tf[j]; }
            oL[j] = vL; oH[j] = vH;
        }
        int rL = row0 + ty * 8 + 2 * i2;
        float4* ypL = (float4*)(Y + (size_t)rL * CC + col0 + tx * 8);
        ypL[0] = make_float4(oL[0], oL[1], oL[2], oL[3]);
        ypL[1] = make_float4(oL[4], oL[5], oL[6], oL[7]);
        float4* ypH = (float4*)(Y + (size_t)(rL + 1) * CC + col0 + tx * 8);
        ypH[0] = make_float4(oH[0], oH[1], oH[2], oH[3]);
        ypH[1] = make_float4(oH[4], oH[5], oH[6], oH[7]);
    }
}

// ---------------------------------------------------------------------------
extern "C" void kernel_launch(void* const* d_in, const int* in_sizes, int n_in,
                              void* d_out, int out_size) {
    const int*   node_c     = (const int*)d_in[0];
    const int*   cond_c     = (const int*)d_in[1];
    const float* cond_feats = (const float*)d_in[2];
    const float* t          = (const float*)d_in[3];
    const float* W_proj     = (const float*)d_in[4];
    const float* b_proj     = (const float*)d_in[5];
    const float* W_l1       = (const float*)d_in[6];
    const float* b_l1       = (const float*)d_in[7];
    const float* W_l2       = (const float*)d_in[8];
    const float* b_l2       = (const float*)d_in[9];
    const float* W_t1       = (const float*)d_in[10];
    const float* b_t1       = (const float*)d_in[11];
    const float* W_t2       = (const float*)d_in[12];
    const float* b_t2       = (const float*)d_in[13];
    float* out = (float*)d_out;

    float* h1; cudaGetSymbolAddress((void**)&h1, g_h1);
    float* h2; cudaGetSymbolAddress((void**)&h2, g_h2);
    float* fa; cudaGetSymbolAddress((void**)&fa, g_favg);

    k_prep<<<MM / 256, 256>>>(cond_c);
    k_tfeats<<<1, 256>>>(t, W_t1, b_t1, W_t2, b_t2);

    k_knn<<<NN / 16, 256>>>(node_c, cond_feats);   // 1024 blocks, 8 warps x 2 nodes

    dim3 gg(NN / 128, CC / 128);   // 128 x 2 = 256 blocks
    k_gemm<0, 0><<<gg, 256>>>(fa, W_proj, b_proj, h1);
    k_gemm<1, 0><<<gg, 256>>>(h1, W_l1, b_l1, h2);
    k_gemm<0, 1><<<gg, 256>>>(h2, W_l2, b_l2, out);

    (void)in_sizes; (void)n_in; (void)out_size;
}